// round 7
// baseline (speedup 1.0000x reference)
#include <cuda_runtime.h>

// dis_loss: mean over (B*21) per-joint Euclidean distances of [B,21,3] fp32.
// Pure HBM-streaming reduction: 132 MB read, 4 B write.
// Persistent single-wave grid (148 SMs x 8 CTAs) + grid-stride loop:
// amortizes the block-reduction tail and removes wave transitions.

#define B_ROWS      262144
#define N_JOINTS    21
#define TOTAL_F     (B_ROWS * N_JOINTS * 3)        // 16,515,072 floats per tensor
#define FLOATS_PER_UNIT 12                         // 4 joints = 3 float4 per tensor
#define UNITS       (TOTAL_F / FLOATS_PER_UNIT)    // 1,376,256 (exact)
#define THREADS     256
#define GRID        1184                           // 148 SMs x 8 CTAs: one full wave

__device__ float    g_acc;    // zeroed at module load; reset by last block each launch
__device__ unsigned g_count;

__device__ __forceinline__ float joint_dist(float dx, float dy, float dz) {
    return sqrtf(fmaf(dx, dx, fmaf(dy, dy, dz * dz)));
}

// One unit = 12 consecutive floats = 4 joints (x,y,z triples), float4-aligned.
__device__ __forceinline__ float process_unit(const float4* __restrict__ pred,
                                              const float4* __restrict__ tgt,
                                              int i) {
    const int base = i * 3;
    float4 p0 = __ldcs(&pred[base + 0]);
    float4 p1 = __ldcs(&pred[base + 1]);
    float4 p2 = __ldcs(&pred[base + 2]);
    float4 t0 = __ldcs(&tgt[base + 0]);
    float4 t1 = __ldcs(&tgt[base + 1]);
    float4 t2 = __ldcs(&tgt[base + 2]);

    float s;
    s  = joint_dist(p0.x - t0.x, p0.y - t0.y, p0.z - t0.z);
    s += joint_dist(p0.w - t0.w, p1.x - t1.x, p1.y - t1.y);
    s += joint_dist(p1.z - t1.z, p1.w - t1.w, p2.x - t2.x);
    s += joint_dist(p2.y - t2.y, p2.z - t2.z, p2.w - t2.w);
    return s;
}

__global__ void __launch_bounds__(THREADS)
dis_loss_kernel(const float4* __restrict__ pred,
                const float4* __restrict__ tgt,
                float* __restrict__ out) {
    const int idx    = blockIdx.x * THREADS + threadIdx.x;
    const int stride = GRID * THREADS;      // 303,104

    // Grid-stride, unrolled x2: 12 independent LDG.128 in flight per thread.
    float s = 0.0f;
    int i = idx;
    for (; i + stride < UNITS; i += 2 * stride) {
        float a = process_unit(pred, tgt, i);
        float b = process_unit(pred, tgt, i + stride);
        s += a + b;
    }
    if (i < UNITS)
        s += process_unit(pred, tgt, i);

    // Warp reduction
    #pragma unroll
    for (int off = 16; off > 0; off >>= 1)
        s += __shfl_xor_sync(0xFFFFFFFFu, s, off);

    // Block reduction
    __shared__ float warp_sums[THREADS / 32];
    const int lane = threadIdx.x & 31;
    const int warp = threadIdx.x >> 5;
    if (lane == 0) warp_sums[warp] = s;
    __syncthreads();

    __shared__ bool is_last;
    if (threadIdx.x == 0) {
        float bsum = 0.0f;
        #pragma unroll
        for (int w = 0; w < THREADS / 32; w++) bsum += warp_sums[w];
        atomicAdd(&g_acc, bsum);
        __threadfence();
        unsigned prev = atomicAdd(&g_count, 1u);
        is_last = (prev == (unsigned)(GRID - 1));
    }
    __syncthreads();

    // Last block finalizes and resets state for the next graph replay.
    if (is_last && threadIdx.x == 0) {
        float total = atomicAdd(&g_acc, 0.0f);  // serialized-visible read
        out[0] = total * (1.0f / (float)((long long)B_ROWS * N_JOINTS));
        g_acc   = 0.0f;
        g_count = 0u;
    }
}

extern "C" void kernel_launch(void* const* d_in, const int* in_sizes, int n_in,
                              void* d_out, int out_size) {
    const float4* pred = (const float4*)d_in[0];
    const float4* tgt  = (const float4*)d_in[1];
    float* out = (float*)d_out;
    dis_loss_kernel<<<GRID, THREADS>>>(pred, tgt, out);
}

// round 8
// speedup vs baseline: 1.0238x; 1.0238x over previous
#include <cuda_runtime.h>

// dis_loss: mean over (B*21) per-joint Euclidean distances of [B,21,3] fp32.
// Pure HBM-streaming reduction: 132 MB read, 4 B write.
// Persistent single-wave grid (148 SMs x 8 CTAs) + grid-stride loop:
// amortizes the block-reduction tail and removes wave transitions.

#define B_ROWS      262144
#define N_JOINTS    21
#define TOTAL_F     (B_ROWS * N_JOINTS * 3)        // 16,515,072 floats per tensor
#define FLOATS_PER_UNIT 12                         // 4 joints = 3 float4 per tensor
#define UNITS       (TOTAL_F / FLOATS_PER_UNIT)    // 1,376,256 (exact)
#define THREADS     256
#define GRID        1184                           // 148 SMs x 8 CTAs: one full wave

__device__ float    g_acc;    // zeroed at module load; reset by last block each launch
__device__ unsigned g_count;

__device__ __forceinline__ float joint_dist(float dx, float dy, float dz) {
    return sqrtf(fmaf(dx, dx, fmaf(dy, dy, dz * dz)));
}

// One unit = 12 consecutive floats = 4 joints (x,y,z triples), float4-aligned.
__device__ __forceinline__ float process_unit(const float4* __restrict__ pred,
                                              const float4* __restrict__ tgt,
                                              int i) {
    const int base = i * 3;
    float4 p0 = __ldcs(&pred[base + 0]);
    float4 p1 = __ldcs(&pred[base + 1]);
    float4 p2 = __ldcs(&pred[base + 2]);
    float4 t0 = __ldcs(&tgt[base + 0]);
    float4 t1 = __ldcs(&tgt[base + 1]);
    float4 t2 = __ldcs(&tgt[base + 2]);

    float s;
    s  = joint_dist(p0.x - t0.x, p0.y - t0.y, p0.z - t0.z);
    s += joint_dist(p0.w - t0.w, p1.x - t1.x, p1.y - t1.y);
    s += joint_dist(p1.z - t1.z, p1.w - t1.w, p2.x - t2.x);
    s += joint_dist(p2.y - t2.y, p2.z - t2.z, p2.w - t2.w);
    return s;
}

__global__ void __launch_bounds__(THREADS)
dis_loss_kernel(const float4* __restrict__ pred,
                const float4* __restrict__ tgt,
                float* __restrict__ out) {
    const int idx    = blockIdx.x * THREADS + threadIdx.x;
    const int stride = GRID * THREADS;      // 303,104

    // Grid-stride, unrolled x2: 12 independent LDG.128 in flight per thread.
    float s = 0.0f;
    int i = idx;
    for (; i + stride < UNITS; i += 2 * stride) {
        float a = process_unit(pred, tgt, i);
        float b = process_unit(pred, tgt, i + stride);
        s += a + b;
    }
    if (i < UNITS)
        s += process_unit(pred, tgt, i);

    // Warp reduction
    #pragma unroll
    for (int off = 16; off > 0; off >>= 1)
        s += __shfl_xor_sync(0xFFFFFFFFu, s, off);

    // Block reduction
    __shared__ float warp_sums[THREADS / 32];
    const int lane = threadIdx.x & 31;
    const int warp = threadIdx.x >> 5;
    if (lane == 0) warp_sums[warp] = s;
    __syncthreads();

    __shared__ bool is_last;
    if (threadIdx.x == 0) {
        float bsum = 0.0f;
        #pragma unroll
        for (int w = 0; w < THREADS / 32; w++) bsum += warp_sums[w];
        atomicAdd(&g_acc, bsum);
        __threadfence();
        unsigned prev = atomicAdd(&g_count, 1u);
        is_last = (prev == (unsigned)(GRID - 1));
    }
    __syncthreads();

    // Last block finalizes and resets state for the next graph replay.
    if (is_last && threadIdx.x == 0) {
        float total = atomicAdd(&g_acc, 0.0f);  // serialized-visible read
        out[0] = total * (1.0f / (float)((long long)B_ROWS * N_JOINTS));
        g_acc   = 0.0f;
        g_count = 0u;
    }
}

extern "C" void kernel_launch(void* const* d_in, const int* in_sizes, int n_in,
                              void* d_out, int out_size) {
    const float4* pred = (const float4*)d_in[0];
    const float4* tgt  = (const float4*)d_in[1];
    float* out = (float*)d_out;
    dis_loss_kernel<<<GRID, THREADS>>>(pred, tgt, out);
}